// round 10
// baseline (speedup 1.0000x reference)
#include <cuda_runtime.h>
#include <cuda_bf16.h>
#include <math.h>
#include <stdint.h>

#define MTOT 131072
#define SPATIAL 128

__device__ __align__(256) __nv_bfloat16 g_qkv[(size_t)MTOT * 384];
__device__ __align__(256) __nv_bfloat16 g_o  [(size_t)MTOT * 128];
__device__ __align__(256) __nv_bfloat16 g_h  [(size_t)MTOT * 512];
__device__ __align__(256) __nv_bfloat16 g_wt [786432];  // 4 layers x 12 images x [128n][128k]

__device__ __forceinline__ float gelu_exact(float a) {
    return 0.5f * a * (1.0f + erff(a * 0.70710678118654752440f));
}

__device__ __forceinline__ uint32_t smem_u32(const void* p) {
    uint32_t a;
    asm("{ .reg .u64 t; cvta.to.shared.u64 t, %1; cvt.u32.u64 %0, t; }" : "=r"(a) : "l"(p));
    return a;
}

#define LDSM4(r0, r1, r2, r3, addr) \
    asm volatile("ldmatrix.sync.aligned.m8n8.x4.shared.b16 {%0,%1,%2,%3}, [%4];" \
                 : "=r"(r0), "=r"(r1), "=r"(r2), "=r"(r3) : "r"(addr))

#define MMA16816(d, a, b) \
    asm volatile("mma.sync.aligned.m16n8k16.row.col.f32.bf16.bf16.f32 " \
                 "{%0,%1,%2,%3},{%4,%5,%6,%7},{%8,%9},{%0,%1,%2,%3};" \
                 : "+f"((d)[0]), "+f"((d)[1]), "+f"((d)[2]), "+f"((d)[3]) \
                 : "r"((a)[0]), "r"((a)[1]), "r"((a)[2]), "r"((a)[3]), \
                   "r"((b)[0]), "r"((b)[1]))

// ---------------------------------------------------------------------------
// Prep: transpose weights to n-major/k-contig bf16 images [128n][128k].
// Per layer (12 imgs): 0-2 qkv n-blocks, 3 proj, 4-7 ff1 n-blocks, 8-11 ff2 k-chunks.
// ---------------------------------------------------------------------------
__global__ __launch_bounds__(256) void k_prep(
    const float* __restrict__ qkv_w, const float* __restrict__ out_w,
    const float* __restrict__ ff_w1, const float* __restrict__ ff_w2)
{
    const int idx = blockIdx.x * 256 + threadIdx.x;   // 0..786431
    const int d   = idx / 196608;
    const int rem = idx % 196608;
    const int img = rem / 16384;
    const int pos = rem % 16384;
    const int n = pos >> 7, k = pos & 127;
    float val;
    if (img < 3)       val = qkv_w[(size_t)(d * 128 + k) * 384 + img * 128 + n];
    else if (img == 3) val = out_w[(size_t)(d * 128 + k) * 128 + n];
    else if (img < 8)  val = ff_w1[(size_t)(d * 128 + k) * 512 + (img - 4) * 128 + n];
    else               val = ff_w2[(size_t)(d * 512 + (img - 8) * 128 + k) * 128 + n];
    g_wt[idx] = __float2bfloat16(val);
}

// ---------------------------------------------------------------------------
// Unified warp-MMA bf16 GEMM. CTA = 64 tokens, 256 threads (8 warps, 2M x 4N),
// warp tile 32x32 -> acc 32 regs/thread -> target 3 CTAs/SM.
// NB n-blocks of 128; KC k-chunks of 128. SRC: 0=X(+LN), 1=g_o, 2=g_h.
// EPI: 0 -> g_qkv (bf16); 1 -> g_h = gelu(v+b) (bf16); 2 -> Xout += v+b (fp32).
// smem: A [64][136] bf16 @0 (17408 B), B [128][136] bf16 @17408. Total 52224 B.
// Row stride 272 B -> conflict-free ldmatrix (16*l mod 128 distinct over 8 rows).
// ---------------------------------------------------------------------------
template<int NB, int KC, int SRC, int EPI, int IMG0>
__global__ void __launch_bounds__(256, 3) k_tg(
    const float* __restrict__ X, const float* __restrict__ gamma,
    const float* __restrict__ beta, const float* __restrict__ bias,
    float* __restrict__ Xout, int d)
{
    extern __shared__ char smem[];
    const uint32_t sbA = smem_u32(smem);
    const uint32_t sbB = sbA + 17408;
    const int tid = threadIdx.x, wid = tid >> 5, lane = tid & 31;
    const int wm = wid >> 2, wn = wid & 3;            // 2 M-warps x 4 N-warps
    const int m0 = blockIdx.x * 64;

    const __nv_bfloat16* wt = g_wt + (size_t)d * 196608 + (size_t)IMG0 * 16384;

    const uint32_t aBase = sbA + (uint32_t)((wm * 32 + (lane & 15)) * 272 + (lane >> 4) * 16);
    const uint32_t bBase = sbB + (uint32_t)((wn * 32 + ((lane >> 4) * 8) + (lane & 7)) * 272
                                            + ((lane >> 3) & 1) * 16);

    for (int nb = 0; nb < NB; nb++) {
        float acc[2][4][4];
#pragma unroll
        for (int mt = 0; mt < 2; mt++)
#pragma unroll
            for (int nt = 0; nt < 4; nt++)
#pragma unroll
                for (int f = 0; f < 4; f++) acc[mt][nt][f] = 0.f;

        for (int kc = 0; kc < KC; kc++) {
            if (nb > 0 || kc > 0) __syncthreads();

            {   // ---- stage B: [128][128] bf16 image -> padded smem ----
                const uint4* s4 = (const uint4*)(wt + (size_t)(nb * KC + kc) * 16384);
                char* bs = smem + 17408;
#pragma unroll
                for (int i = 0; i < 8; i++) {
                    const int u = tid + i * 256;        // 2048 x 16B
                    const int row = u >> 4, c8 = u & 15;
                    *(uint4*)(bs + (size_t)row * 272 + c8 * 16) = s4[u];
                }
            }
            if ((KC == 1 && nb == 0) || KC > 1) {      // ---- stage A (64 rows) ----
                const int m = tid >> 2, q = tid & 3;   // 4 threads per row, 32 cols each
                if (SRC == 0) {                        // LN(x) fused, fp32 -> bf16
                    const float* ap = X + (size_t)(m0 + m) * 128 + q * 32;
                    float4 v[8];
#pragma unroll
                    for (int j = 0; j < 8; j++) v[j] = ((const float4*)ap)[j];
                    float s = 0.f, sq = 0.f;
#pragma unroll
                    for (int j = 0; j < 8; j++) {
                        s  += v[j].x + v[j].y + v[j].z + v[j].w;
                        sq += v[j].x*v[j].x + v[j].y*v[j].y + v[j].z*v[j].z + v[j].w*v[j].w;
                    }
                    s  += __shfl_xor_sync(0xffffffffu, s , 1);
                    sq += __shfl_xor_sync(0xffffffffu, sq, 1);
                    s  += __shfl_xor_sync(0xffffffffu, s , 2);
                    sq += __shfl_xor_sync(0xffffffffu, sq, 2);
                    const float mean = s * (1.f / 128.f);
                    const float rstd = rsqrtf(sq * (1.f / 128.f) - mean * mean + 1e-3f);
                    char* arow = smem + (size_t)m * 272 + q * 64;
#pragma unroll
                    for (int j = 0; j < 4; j++) {
                        const int k = q * 32 + j * 8;
                        const float4 f0 = v[2*j], f1 = v[2*j+1];
                        const float4 g0 = *(const float4*)(gamma + k);
                        const float4 g1 = *(const float4*)(gamma + k + 4);
                        const float4 b0 = *(const float4*)(beta + k);
                        const float4 b1 = *(const float4*)(beta + k + 4);
                        __nv_bfloat16 t8[8];
                        t8[0]=__float2bfloat16((f0.x-mean)*rstd*g0.x+b0.x);
                        t8[1]=__float2bfloat16((f0.y-mean)*rstd*g0.y+b0.y);
                        t8[2]=__float2bfloat16((f0.z-mean)*rstd*g0.z+b0.z);
                        t8[3]=__float2bfloat16((f0.w-mean)*rstd*g0.w+b0.w);
                        t8[4]=__float2bfloat16((f1.x-mean)*rstd*g1.x+b1.x);
                        t8[5]=__float2bfloat16((f1.y-mean)*rstd*g1.y+b1.y);
                        t8[6]=__float2bfloat16((f1.z-mean)*rstd*g1.z+b1.z);
                        t8[7]=__float2bfloat16((f1.w-mean)*rstd*g1.w+b1.w);
                        *(uint4*)(arow + j * 16) = *(const uint4*)t8;
                    }
                } else {                               // direct bf16 copy
                    const __nv_bfloat16* ap = (SRC == 1)
                        ? g_o + (size_t)(m0 + m) * 128 + q * 32
                        : g_h + (size_t)(m0 + m) * 512 + kc * 128 + q * 32;
                    char* arow = smem + (size_t)m * 272 + q * 64;
#pragma unroll
                    for (int j = 0; j < 4; j++)
                        *(uint4*)(arow + j * 16) = ((const uint4*)ap)[j];
                }
            }
            __syncthreads();

            // ---- compute: 8 k-steps of m16n8k16 ----
#pragma unroll
            for (int kk = 0; kk < 8; kk++) {
                uint32_t a[2][4];
#pragma unroll
                for (int mt = 0; mt < 2; mt++)
                    LDSM4(a[mt][0], a[mt][1], a[mt][2], a[mt][3],
                          aBase + (uint32_t)(mt * 16 * 272 + kk * 32));
                uint32_t b[4][2];
#pragma unroll
                for (int nt2 = 0; nt2 < 2; nt2++)
                    LDSM4(b[nt2*2][0], b[nt2*2][1], b[nt2*2+1][0], b[nt2*2+1][1],
                          bBase + (uint32_t)(nt2 * 16 * 272 + kk * 32));
#pragma unroll
                for (int mt = 0; mt < 2; mt++)
#pragma unroll
                    for (int nt = 0; nt < 4; nt++)
                        MMA16816(acc[mt][nt], a[mt], b[nt]);
            }
        }

        // ---- epilogue ----
#pragma unroll
        for (int mt = 0; mt < 2; mt++) {
#pragma unroll
            for (int nt = 0; nt < 4; nt++) {
                const int r = m0 + wm * 32 + mt * 16 + (lane >> 2);
                const int c = nb * 128 + wn * 32 + nt * 8 + (lane & 3) * 2;
                float2 bv = make_float2(0.f, 0.f);
                if (EPI != 0) bv = *(const float2*)(bias + c);
#pragma unroll
                for (int hrow = 0; hrow < 2; hrow++) {
                    const size_t row = (size_t)(r + hrow * 8);
                    const float u0 = acc[mt][nt][hrow*2+0], u1 = acc[mt][nt][hrow*2+1];
                    if (EPI == 0) {
                        *(__nv_bfloat162*)(g_qkv + row * 384 + c) =
                            __floats2bfloat162_rn(u0, u1);
                    } else if (EPI == 1) {
                        *(__nv_bfloat162*)(g_h + row * 512 + c) =
                            __floats2bfloat162_rn(gelu_exact(u0 + bv.x), gelu_exact(u1 + bv.y));
                    } else {
                        float2 xo = *(float2*)(Xout + row * 128 + c);
                        *(float2*)(Xout + row * 128 + c) =
                            make_float2(xo.x + u0 + bv.x, xo.y + u1 + bv.y);
                    }
                }
            }
        }
    }
}

// ---------------------------------------------------------------------------
// Local 3x3 attention: bf16 global traffic, fp32 smem compute. (unchanged)
// ---------------------------------------------------------------------------
__global__ __launch_bounds__(256) void k_attn()
{
    extern __shared__ float sm[];
    float* ksh = sm;              // 18*18*36
    float* vsh = sm + 11664;
    float* qo  = sm + 2 * 11664;  // 256*36
    const int tid = threadIdx.x;
    const int b   = blockIdx.z;
    const int ti0 = blockIdx.y * 16, tj0 = blockIdx.x * 16;
    const size_t img_base = (size_t)b * (SPATIAL * SPATIAL);

    for (int head = 0; head < 4; head++) {
        if (head) __syncthreads();
        const int qoff = head * 32, koff = 128 + head * 32, voff = 256 + head * 32;
        for (int idx = tid; idx < 18 * 18 * 16; idx += 256) {
            const int c2 = (idx & 15) * 2;
            const int rc = idx >> 4;
            const int r = rc / 18, cl = rc % 18;
            const int gi = ti0 + r - 1, gj = tj0 + cl - 1;
            float k0 = 0.f, k1 = 0.f, v0 = 0.f, v1 = 0.f;
            if (gi >= 0 && gi < SPATIAL && gj >= 0 && gj < SPATIAL) {
                const __nv_bfloat16* p = g_qkv + (img_base + (size_t)gi * SPATIAL + gj) * 384;
                const __nv_bfloat162 kp = *(const __nv_bfloat162*)(p + koff + c2);
                const __nv_bfloat162 vp = *(const __nv_bfloat162*)(p + voff + c2);
                k0 = __bfloat162float(kp.x); k1 = __bfloat162float(kp.y);
                v0 = __bfloat162float(vp.x); v1 = __bfloat162float(vp.y);
            }
            ksh[rc * 36 + c2] = k0; ksh[rc * 36 + c2 + 1] = k1;
            vsh[rc * 36 + c2] = v0; vsh[rc * 36 + c2 + 1] = v1;
        }
        for (int idx = tid; idx < 256 * 16; idx += 256) {
            const int c2 = (idx & 15) * 2, t = idx >> 4;
            const int gi = ti0 + (t >> 4), gj = tj0 + (t & 15);
            const __nv_bfloat162 qp = *(const __nv_bfloat162*)(
                g_qkv + (img_base + (size_t)gi * SPATIAL + gj) * 384 + qoff + c2);
            qo[t * 36 + c2] = __bfloat162float(qp.x);
            qo[t * 36 + c2 + 1] = __bfloat162float(qp.y);
        }
        __syncthreads();

        const int t = tid, lti = t >> 4, ltj = t & 15;
        float q[32];
#pragma unroll
        for (int i = 0; i < 8; i++) {
            float4 f = *(const float4*)&qo[t * 36 + i * 4];
            q[4*i+0]=f.x; q[4*i+1]=f.y; q[4*i+2]=f.z; q[4*i+3]=f.w;
        }
        float lg[9];
#pragma unroll
        for (int nb = 0; nb < 9; nb++) {
            const float* kp = &ksh[((lti + nb/3)*18 + (ltj + nb%3))*36];
            float dd = 0.f;
#pragma unroll
            for (int i = 0; i < 8; i++) {
                float4 f = *(const float4*)&kp[i*4];
                dd += q[4*i]*f.x + q[4*i+1]*f.y + q[4*i+2]*f.z + q[4*i+3]*f.w;
            }
            lg[nb] = dd * 0.17677669529663687f;
        }
        float mx = lg[0];
#pragma unroll
        for (int nb = 1; nb < 9; nb++) mx = fmaxf(mx, lg[nb]);
        float p9[9], Z = 0.f;
#pragma unroll
        for (int nb = 0; nb < 9; nb++) { p9[nb] = expf(lg[nb] - mx); Z += p9[nb]; }
        const float inv = 1.f / Z;
        float o[32] = {};
#pragma unroll
        for (int nb = 0; nb < 9; nb++) {
            const float wgt = p9[nb] * inv;
            const float* vp = &vsh[((lti + nb/3)*18 + (ltj + nb%3))*36];
#pragma unroll
            for (int i = 0; i < 8; i++) {
                float4 f = *(const float4*)&vp[i*4];
                o[4*i+0]+=wgt*f.x; o[4*i+1]+=wgt*f.y; o[4*i+2]+=wgt*f.z; o[4*i+3]+=wgt*f.w;
            }
        }
#pragma unroll
        for (int i = 0; i < 8; i++)
            *(float4*)&qo[t*36 + i*4] = make_float4(o[4*i], o[4*i+1], o[4*i+2], o[4*i+3]);
        __syncthreads();
        for (int idx = tid; idx < 256 * 16; idx += 256) {
            const int c2 = (idx & 15) * 2, tt = idx >> 4;
            const int gi = ti0 + (tt >> 4), gj = tj0 + (tt & 15);
            *(__nv_bfloat162*)(g_o + (img_base + (size_t)gi * SPATIAL + gj) * 128
                               + head * 32 + c2) =
                __floats2bfloat162_rn(qo[tt * 36 + c2], qo[tt * 36 + c2 + 1]);
        }
    }
}

// ---------------------------------------------------------------------------
extern "C" void kernel_launch(void* const* d_in, const int* in_sizes, int n_in,
                              void* d_out, int out_size)
{
    (void)in_sizes; (void)n_in; (void)out_size;
    const float* x_in  = (const float*)d_in[0];
    const float* ln1_g = (const float*)d_in[1];
    const float* ln1_b = (const float*)d_in[2];
    const float* qkv_w = (const float*)d_in[3];
    const float* out_w = (const float*)d_in[4];
    const float* out_b = (const float*)d_in[5];
    const float* ln2_g = (const float*)d_in[6];
    const float* ln2_b = (const float*)d_in[7];
    const float* ff_w1 = (const float*)d_in[8];
    const float* ff_b1 = (const float*)d_in[9];
    const float* ff_w2 = (const float*)d_in[10];
    const float* ff_b2 = (const float*)d_in[11];
    float* X = (float*)d_out;

    const int SM_TG   = 52224;
    const int SM_ATTN = (2 * 11664 + 9216) * 4;
    cudaFuncSetAttribute(k_tg<3,1,0,0,0>, cudaFuncAttributeMaxDynamicSharedMemorySize, SM_TG);
    cudaFuncSetAttribute(k_tg<1,1,1,2,3>, cudaFuncAttributeMaxDynamicSharedMemorySize, SM_TG);
    cudaFuncSetAttribute(k_tg<4,1,0,1,4>, cudaFuncAttributeMaxDynamicSharedMemorySize, SM_TG);
    cudaFuncSetAttribute(k_tg<1,4,2,2,8>, cudaFuncAttributeMaxDynamicSharedMemorySize, SM_TG);
    cudaFuncSetAttribute(k_attn, cudaFuncAttributeMaxDynamicSharedMemorySize, SM_ATTN);

    cudaMemcpyAsync(X, x_in, (size_t)MTOT * 128 * sizeof(float),
                    cudaMemcpyDeviceToDevice, 0);
    k_prep<<<3072, 256>>>(qkv_w, out_w, ff_w1, ff_w2);

    const int GB = MTOT / 64;    // 2048 CTAs
    dim3 gAttn(8, 8, 8);
    for (int d = 0; d < 4; d++) {
        k_tg<3,1,0,0,0><<<GB, 256, SM_TG>>>(X, ln1_g + d*128, ln1_b + d*128, out_b, X, d);
        k_attn<<<gAttn, 256, SM_ATTN>>>();
        k_tg<1,1,1,2,3><<<GB, 256, SM_TG>>>(X, ln1_g, ln1_b, out_b + d*128, X, d);
        k_tg<4,1,0,1,4><<<GB, 256, SM_TG>>>(X, ln2_g + d*128, ln2_b + d*128, ff_b1 + d*512, X, d);
        k_tg<1,4,2,2,8><<<GB, 256, SM_TG>>>(X, ln2_g, ln2_b, ff_b2 + d*128, X, d);
    }
}

// round 11
// speedup vs baseline: 1.0955x; 1.0955x over previous
#include <cuda_runtime.h>
#include <cuda_bf16.h>
#include <math.h>
#include <stdint.h>

#define MTOT 131072
#define SPATIAL 128

__device__ __align__(256) __nv_bfloat16 g_qkv[(size_t)MTOT * 384];
__device__ __align__(256) __nv_bfloat16 g_o  [(size_t)MTOT * 128];
__device__ __align__(256) __nv_bfloat16 g_wt [786432];  // 4 layers x 12 images x [128n][128k]

__device__ __forceinline__ float gelu_exact(float a) {
    return 0.5f * a * (1.0f + erff(a * 0.70710678118654752440f));
}

__device__ __forceinline__ uint32_t smem_u32(const void* p) {
    uint32_t a;
    asm("{ .reg .u64 t; cvta.to.shared.u64 t, %1; cvt.u32.u64 %0, t; }" : "=r"(a) : "l"(p));
    return a;
}

#define LDSM4(r0, r1, r2, r3, addr) \
    asm volatile("ldmatrix.sync.aligned.m8n8.x4.shared.b16 {%0,%1,%2,%3}, [%4];" \
                 : "=r"(r0), "=r"(r1), "=r"(r2), "=r"(r3) : "r"(addr))

#define MMA16816(d, a, b) \
    asm volatile("mma.sync.aligned.m16n8k16.row.col.f32.bf16.bf16.f32 " \
                 "{%0,%1,%2,%3},{%4,%5,%6,%7},{%8,%9},{%0,%1,%2,%3};" \
                 : "+f"((d)[0]), "+f"((d)[1]), "+f"((d)[2]), "+f"((d)[3]) \
                 : "r"((a)[0]), "r"((a)[1]), "r"((a)[2]), "r"((a)[3]), \
                   "r"((b)[0]), "r"((b)[1]))

// ---------------------------------------------------------------------------
// Prep: transpose weights to n-major/k-contig bf16 images [128n][128k].
// Per layer (12 imgs): 0-2 qkv n-blocks, 3 proj, 4-7 ff1 n-blocks, 8-11 ff2 k-chunks.
// ---------------------------------------------------------------------------
__global__ __launch_bounds__(256) void k_prep(
    const float* __restrict__ qkv_w, const float* __restrict__ out_w,
    const float* __restrict__ ff_w1, const float* __restrict__ ff_w2)
{
    const int idx = blockIdx.x * 256 + threadIdx.x;   // 0..786431
    const int d   = idx / 196608;
    const int rem = idx % 196608;
    const int img = rem / 16384;
    const int pos = rem % 16384;
    const int n = pos >> 7, k = pos & 127;
    float val;
    if (img < 3)       val = qkv_w[(size_t)(d * 128 + k) * 384 + img * 128 + n];
    else if (img == 3) val = out_w[(size_t)(d * 128 + k) * 128 + n];
    else if (img < 8)  val = ff_w1[(size_t)(d * 128 + k) * 512 + (img - 4) * 128 + n];
    else               val = ff_w2[(size_t)(d * 512 + (img - 8) * 128 + k) * 128 + n];
    g_wt[idx] = __float2bfloat16(val);
}

// ---------------------------------------------------------------------------
// Shared helpers for the MMA kernels (CTA = 64 tokens, 8 warps 2M x 4N).
// A/B/H smem tiles use row stride 272 B -> conflict-free ldmatrix.
// ---------------------------------------------------------------------------
__device__ __forceinline__ void stage_B(char* bs, const __nv_bfloat16* img, int tid) {
    const uint4* s4 = (const uint4*)img;
#pragma unroll
    for (int i = 0; i < 8; i++) {
        const int u = tid + i * 256;            // 2048 x 16B
        const int row = u >> 4, c8 = u & 15;
        *(uint4*)(bs + (size_t)row * 272 + c8 * 16) = s4[u];
    }
}

// One 64x128 @ 128x128 warp-MMA pass: acc += A(smem) * B(smem)^T
__device__ __forceinline__ void gemm_64x128(
    float acc[2][4][4], uint32_t aBase, uint32_t bBase)
{
#pragma unroll
    for (int kk = 0; kk < 8; kk++) {
        uint32_t a[2][4];
#pragma unroll
        for (int mt = 0; mt < 2; mt++)
            LDSM4(a[mt][0], a[mt][1], a[mt][2], a[mt][3],
                  aBase + (uint32_t)(mt * 16 * 272 + kk * 32));
        uint32_t b[4][2];
#pragma unroll
        for (int nt2 = 0; nt2 < 2; nt2++)
            LDSM4(b[nt2*2][0], b[nt2*2][1], b[nt2*2+1][0], b[nt2*2+1][1],
                  bBase + (uint32_t)(nt2 * 16 * 272 + kk * 32));
#pragma unroll
        for (int mt = 0; mt < 2; mt++)
#pragma unroll
            for (int nt = 0; nt < 4; nt++)
                MMA16816(acc[mt][nt], a[mt], b[nt]);
    }
}

// ---------------------------------------------------------------------------
// Kernel 1: y = LN1(x); qkv = y @ Wqkv (3 n-blocks) -> g_qkv bf16.
// smem: A 17408 + B 34816 = 52224 B.
// ---------------------------------------------------------------------------
__global__ void __launch_bounds__(256, 3) k_qkv(
    const float* __restrict__ X, const float* __restrict__ gamma,
    const float* __restrict__ beta, int d)
{
    extern __shared__ char smem[];
    const uint32_t sbA = smem_u32(smem);
    const uint32_t sbB = sbA + 17408;
    const int tid = threadIdx.x, wid = tid >> 5, lane = tid & 31;
    const int wm = wid >> 2, wn = wid & 3;
    const int m0 = blockIdx.x * 64;
    const __nv_bfloat16* wt = g_wt + (size_t)d * 196608;

    const uint32_t aBase = sbA + (uint32_t)((wm * 32 + (lane & 15)) * 272 + (lane >> 4) * 16);
    const uint32_t bBase = sbB + (uint32_t)((wn * 32 + ((lane >> 4) * 8) + (lane & 7)) * 272
                                            + ((lane >> 3) & 1) * 16);

    {   // stage A: LN1(x) -> bf16
        const int m = tid >> 2, q = tid & 3;
        const float* ap = X + (size_t)(m0 + m) * 128 + q * 32;
        float4 v[8];
#pragma unroll
        for (int j = 0; j < 8; j++) v[j] = ((const float4*)ap)[j];
        float s = 0.f, sq = 0.f;
#pragma unroll
        for (int j = 0; j < 8; j++) {
            s  += v[j].x + v[j].y + v[j].z + v[j].w;
            sq += v[j].x*v[j].x + v[j].y*v[j].y + v[j].z*v[j].z + v[j].w*v[j].w;
        }
        s  += __shfl_xor_sync(0xffffffffu, s , 1);
        sq += __shfl_xor_sync(0xffffffffu, sq, 1);
        s  += __shfl_xor_sync(0xffffffffu, s , 2);
        sq += __shfl_xor_sync(0xffffffffu, sq, 2);
        const float mean = s * (1.f / 128.f);
        const float rstd = rsqrtf(sq * (1.f / 128.f) - mean * mean + 1e-3f);
        char* arow = smem + (size_t)m * 272 + q * 64;
#pragma unroll
        for (int j = 0; j < 4; j++) {
            const int k = q * 32 + j * 8;
            const float4 f0 = v[2*j], f1 = v[2*j+1];
            const float4 g0 = *(const float4*)(gamma + k);
            const float4 g1 = *(const float4*)(gamma + k + 4);
            const float4 b0 = *(const float4*)(beta + k);
            const float4 b1 = *(const float4*)(beta + k + 4);
            __nv_bfloat16 t8[8];
            t8[0]=__float2bfloat16((f0.x-mean)*rstd*g0.x+b0.x);
            t8[1]=__float2bfloat16((f0.y-mean)*rstd*g0.y+b0.y);
            t8[2]=__float2bfloat16((f0.z-mean)*rstd*g0.z+b0.z);
            t8[3]=__float2bfloat16((f0.w-mean)*rstd*g0.w+b0.w);
            t8[4]=__float2bfloat16((f1.x-mean)*rstd*g1.x+b1.x);
            t8[5]=__float2bfloat16((f1.y-mean)*rstd*g1.y+b1.y);
            t8[6]=__float2bfloat16((f1.z-mean)*rstd*g1.z+b1.z);
            t8[7]=__float2bfloat16((f1.w-mean)*rstd*g1.w+b1.w);
            *(uint4*)(arow + j * 16) = *(const uint4*)t8;
        }
    }

    for (int nb = 0; nb < 3; nb++) {
        if (nb) __syncthreads();
        stage_B(smem + 17408, wt + (size_t)nb * 16384, tid);
        __syncthreads();
        float acc[2][4][4] = {};
        gemm_64x128(acc, aBase, bBase);
#pragma unroll
        for (int mt = 0; mt < 2; mt++)
#pragma unroll
            for (int nt = 0; nt < 4; nt++) {
                const int r = m0 + wm * 32 + mt * 16 + (lane >> 2);
                const int c = nb * 128 + wn * 32 + nt * 8 + (lane & 3) * 2;
#pragma unroll
                for (int hrow = 0; hrow < 2; hrow++)
                    *(__nv_bfloat162*)(g_qkv + (size_t)(r + hrow * 8) * 384 + c) =
                        __floats2bfloat162_rn(acc[mt][nt][hrow*2], acc[mt][nt][hrow*2+1]);
            }
    }
}

// ---------------------------------------------------------------------------
// Kernel 3 (FUSED): x += o@Wp + bp; y = LN2(x); h_i = gelu(y@W1_i + b1_i);
// x += sum_i h_i@W2_i + b2.  Post-proj x lives in smem fp32; h never hits DRAM.
// smem: A/y 17408 @0, B 34816 @17408, H 17408 @52224, Xf32 64x132 33792 @69632.
// Total 103424 B -> 2 CTAs/SM.
// ---------------------------------------------------------------------------
__global__ void __launch_bounds__(256, 2) k_fused(
    const float* __restrict__ bp, const float* __restrict__ ln2_g,
    const float* __restrict__ ln2_b, const float* __restrict__ b1,
    const float* __restrict__ b2, float* __restrict__ X, int d)
{
    extern __shared__ char smem[];
    const uint32_t sbA = smem_u32(smem);
    const uint32_t sbB = sbA + 17408;
    const uint32_t sbH = sbA + 52224;
    float* Xs = (float*)(smem + 69632);              // [64][132] fp32
    const int tid = threadIdx.x, wid = tid >> 5, lane = tid & 31;
    const int wm = wid >> 2, wn = wid & 3;
    const int m0 = blockIdx.x * 64;
    const __nv_bfloat16* wt = g_wt + (size_t)d * 196608;

    const uint32_t lA = (uint32_t)((wm * 32 + (lane & 15)) * 272 + (lane >> 4) * 16);
    const uint32_t aBase = sbA + lA;
    const uint32_t hBase = sbH + lA;
    const uint32_t bBase = sbB + (uint32_t)((wn * 32 + ((lane >> 4) * 8) + (lane & 7)) * 272
                                            + ((lane >> 3) & 1) * 16);

    // ---- phase 1: proj ----
    {   // stage A = o tile (bf16 copy), B = proj image
        const int m = tid >> 2, q = tid & 3;
        const __nv_bfloat16* ap = g_o + (size_t)(m0 + m) * 128 + q * 32;
        char* arow = smem + (size_t)m * 272 + q * 64;
#pragma unroll
        for (int j = 0; j < 4; j++)
            *(uint4*)(arow + j * 16) = ((const uint4*)ap)[j];
        stage_B(smem + 17408, wt + 3 * 16384, tid);
    }
    __syncthreads();
    {
        float acc[2][4][4] = {};
        gemm_64x128(acc, aBase, bBase);
        // epilogue: Xs = X_global + acc + bp  (fp32, stride 132)
#pragma unroll
        for (int mt = 0; mt < 2; mt++)
#pragma unroll
            for (int nt = 0; nt < 4; nt++) {
                const int rl = wm * 32 + mt * 16 + (lane >> 2);
                const int c  = wn * 32 + nt * 8 + (lane & 3) * 2;
                const float2 bv = *(const float2*)(bp + c);
#pragma unroll
                for (int hrow = 0; hrow < 2; hrow++) {
                    const int rr = rl + hrow * 8;
                    const float2 xo = *(const float2*)(X + (size_t)(m0 + rr) * 128 + c);
                    *(float2*)&Xs[rr * 132 + c] = make_float2(
                        xo.x + acc[mt][nt][hrow*2]   + bv.x,
                        xo.y + acc[mt][nt][hrow*2+1] + bv.y);
                }
            }
    }
    __syncthreads();

    // ---- phase 2: LN2 from Xs -> y (overwrite A region) ----
    {
        const int m = tid >> 2, q = tid & 3;
        const float* xp = &Xs[m * 132 + q * 32];
        float4 v[8];
#pragma unroll
        for (int j = 0; j < 8; j++) v[j] = ((const float4*)xp)[j];
        float s = 0.f, sq = 0.f;
#pragma unroll
        for (int j = 0; j < 8; j++) {
            s  += v[j].x + v[j].y + v[j].z + v[j].w;
            sq += v[j].x*v[j].x + v[j].y*v[j].y + v[j].z*v[j].z + v[j].w*v[j].w;
        }
        s  += __shfl_xor_sync(0xffffffffu, s , 1);
        sq += __shfl_xor_sync(0xffffffffu, sq, 1);
        s  += __shfl_xor_sync(0xffffffffu, s , 2);
        sq += __shfl_xor_sync(0xffffffffu, sq, 2);
        const float mean = s * (1.f / 128.f);
        const float rstd = rsqrtf(sq * (1.f / 128.f) - mean * mean + 1e-3f);
        char* arow = smem + (size_t)m * 272 + q * 64;
#pragma unroll
        for (int j = 0; j < 4; j++) {
            const int k = q * 32 + j * 8;
            const float4 f0 = v[2*j], f1 = v[2*j+1];
            const float4 g0 = *(const float4*)(ln2_g + k);
            const float4 g1 = *(const float4*)(ln2_g + k + 4);
            const float4 c0 = *(const float4*)(ln2_b + k);
            const float4 c1 = *(const float4*)(ln2_b + k + 4);
            __nv_bfloat16 t8[8];
            t8[0]=__float2bfloat16((f0.x-mean)*rstd*g0.x+c0.x);
            t8[1]=__float2bfloat16((f0.y-mean)*rstd*g0.y+c0.y);
            t8[2]=__float2bfloat16((f0.z-mean)*rstd*g0.z+c0.z);
            t8[3]=__float2bfloat16((f0.w-mean)*rstd*g0.w+c0.w);
            t8[4]=__float2bfloat16((f1.x-mean)*rstd*g1.x+c1.x);
            t8[5]=__float2bfloat16((f1.y-mean)*rstd*g1.y+c1.y);
            t8[6]=__float2bfloat16((f1.z-mean)*rstd*g1.z+c1.z);
            t8[7]=__float2bfloat16((f1.w-mean)*rstd*g1.w+c1.w);
            *(uint4*)(arow + j * 16) = *(const uint4*)t8;
        }
    }

    // ---- phase 3: interleaved ff1/ff2 over 4 128-col chunks ----
    float acc2[2][4][4] = {};
    for (int i = 0; i < 4; i++) {
        __syncthreads();                          // B/H safe to overwrite
        stage_B(smem + 17408, wt + (size_t)(4 + i) * 16384, tid);
        __syncthreads();
        {   // h_i = gelu(y @ W1_i + b1_i) -> H smem (bf16)
            float acc[2][4][4] = {};
            gemm_64x128(acc, aBase, bBase);
#pragma unroll
            for (int mt = 0; mt < 2; mt++)
#pragma unroll
                for (int nt = 0; nt < 4; nt++) {
                    const int rl = wm * 32 + mt * 16 + (lane >> 2);
                    const int c  = wn * 32 + nt * 8 + (lane & 3) * 2;
                    const float2 bv = *(const float2*)(b1 + i * 128 + c);
#pragma unroll
                    for (int hrow = 0; hrow < 2; hrow++) {
                        const int rr = rl + hrow * 8;
                        *(__nv_bfloat162*)(smem + 52224 + (size_t)rr * 272 + c * 2) =
                            __floats2bfloat162_rn(gelu_exact(acc[mt][nt][hrow*2]   + bv.x),
                                                  gelu_exact(acc[mt][nt][hrow*2+1] + bv.y));
                    }
                }
        }
        __syncthreads();                          // H ready; B readers done
        stage_B(smem + 17408, wt + (size_t)(8 + i) * 16384, tid);
        __syncthreads();
        gemm_64x128(acc2, hBase, bBase);          // acc2 += h_i @ W2_i
    }

    // ---- final epilogue: X = Xs + acc2 + b2 ----
#pragma unroll
    for (int mt = 0; mt < 2; mt++)
#pragma unroll
        for (int nt = 0; nt < 4; nt++) {
            const int rl = wm * 32 + mt * 16 + (lane >> 2);
            const int c  = wn * 32 + nt * 8 + (lane & 3) * 2;
            const float2 bv = *(const float2*)(b2 + c);
#pragma unroll
            for (int hrow = 0; hrow < 2; hrow++) {
                const int rr = rl + hrow * 8;
                const float2 xs = *(const float2*)&Xs[rr * 132 + c];
                *(float2*)(X + (size_t)(m0 + rr) * 128 + c) = make_float2(
                    xs.x + acc2[mt][nt][hrow*2]   + bv.x,
                    xs.y + acc2[mt][nt][hrow*2+1] + bv.y);
            }
        }
}

// ---------------------------------------------------------------------------
// Local 3x3 attention: bf16 global traffic, fp32 smem compute. (unchanged)
// ---------------------------------------------------------------------------
__global__ __launch_bounds__(256) void k_attn()
{
    extern __shared__ float sm[];
    float* ksh = sm;              // 18*18*36
    float* vsh = sm + 11664;
    float* qo  = sm + 2 * 11664;  // 256*36
    const int tid = threadIdx.x;
    const int b   = blockIdx.z;
    const int ti0 = blockIdx.y * 16, tj0 = blockIdx.x * 16;
    const size_t img_base = (size_t)b * (SPATIAL * SPATIAL);

    for (int head = 0; head < 4; head++) {
        if (head) __syncthreads();
        const int qoff = head * 32, koff = 128 + head * 32, voff = 256 + head * 32;
        for (int idx = tid; idx < 18 * 18 * 16; idx += 256) {
            const int c2 = (idx & 15) * 2;
            const int rc = idx >> 4;
            const int r = rc / 18, cl = rc % 18;
            const int gi = ti0 + r - 1, gj = tj0 + cl - 1;
            float k0 = 0.f, k1 = 0.f, v0 = 0.f, v1 = 0.f;
            if (gi >= 0 && gi < SPATIAL && gj >= 0 && gj < SPATIAL) {
                const __nv_bfloat16* p = g_qkv + (img_base + (size_t)gi * SPATIAL + gj) * 384;
                const __nv_bfloat162 kp = *(const __nv_bfloat162*)(p + koff + c2);
                const __nv_bfloat162 vp = *(const __nv_bfloat162*)(p + voff + c2);
                k0 = __bfloat162float(kp.x); k1 = __bfloat162float(kp.y);
                v0 = __bfloat162float(vp.x); v1 = __bfloat162float(vp.y);
            }
            ksh[rc * 36 + c2] = k0; ksh[rc * 36 + c2 + 1] = k1;
            vsh[rc * 36 + c2] = v0; vsh[rc * 36 + c2 + 1] = v1;
        }
        for (int idx = tid; idx < 256 * 16; idx += 256) {
            const int c2 = (idx & 15) * 2, t = idx >> 4;
            const int gi = ti0 + (t >> 4), gj = tj0 + (t & 15);
            const __nv_bfloat162 qp = *(const __nv_bfloat162*)(
                g_qkv + (img_base + (size_t)gi * SPATIAL + gj) * 384 + qoff + c2);
            qo[t * 36 + c2] = __bfloat162float(qp.x);
            qo[t * 36 + c2 + 1] = __bfloat162float(qp.y);
        }
        __syncthreads();

        const int t = tid, lti = t >> 4, ltj = t & 15;
        float q[32];
#pragma unroll
        for (int i = 0; i < 8; i++) {
            float4 f = *(const float4*)&qo[t * 36 + i * 4];
            q[4*i+0]=f.x; q[4*i+1]=f.y; q[4*i+2]=f.z; q[4*i+3]=f.w;
        }
        float lg[9];
#pragma unroll
        for (int nb = 0; nb < 9; nb++) {
            const float* kp = &ksh[((lti + nb/3)*18 + (ltj + nb%3))*36];
            float dd = 0.f;
#pragma unroll
            for (int i = 0; i < 8; i++) {
                float4 f = *(const float4*)&kp[i*4];
                dd += q[4*i]*f.x + q[4*i+1]*f.y + q[4*i+2]*f.z + q[4*i+3]*f.w;
            }
            lg[nb] = dd * 0.17677669529663687f;
        }
        float mx = lg[0];
#pragma unroll
        for (int nb = 1; nb < 9; nb++) mx = fmaxf(mx, lg[nb]);
        float p9[9], Z = 0.f;
#pragma unroll
        for (int nb = 0; nb < 9; nb++) { p9[nb] = expf(lg[nb] - mx); Z += p9[nb]; }
        const float inv = 1.f / Z;
        float o[32] = {};
#pragma unroll
        for (int nb = 0; nb < 9; nb++) {
            const float wgt = p9[nb] * inv;
            const float* vp = &vsh[((lti + nb/3)*18 + (ltj + nb%3))*36];
#pragma unroll
            for (int i = 0; i < 8; i++) {
                float4 f = *(const float4*)&vp[i*4];
                o[4*i+0]+=wgt*f.x; o[4*i+1]+=wgt*f.y; o[4*i+2]+=wgt*f.z; o[4*i+3]+=wgt*f.w;
            }
        }
#pragma unroll
        for (int i = 0; i < 8; i++)
            *(float4*)&qo[t*36 + i*4] = make_float4(o[4*i], o[4*i+1], o[4*i+2], o[4*i+3]);
        __syncthreads();
        for (int idx = tid; idx < 256 * 16; idx += 256) {
            const int c2 = (idx & 15) * 2, tt = idx >> 4;
            const int gi = ti0 + (tt >> 4), gj = tj0 + (tt & 15);
            *(__nv_bfloat162*)(g_o + (img_base + (size_t)gi * SPATIAL + gj) * 128
                               + head * 32 + c2) =
                __floats2bfloat162_rn(qo[tt * 36 + c2], qo[tt * 36 + c2 + 1]);
        }
    }
}

// ---------------------------------------------------------------------------
extern "C" void kernel_launch(void* const* d_in, const int* in_sizes, int n_in,
                              void* d_out, int out_size)
{
    (void)in_sizes; (void)n_in; (void)out_size;
    const float* x_in  = (const float*)d_in[0];
    const float* ln1_g = (const float*)d_in[1];
    const float* ln1_b = (const float*)d_in[2];
    const float* qkv_w = (const float*)d_in[3];
    const float* out_w = (const float*)d_in[4];
    const float* out_b = (const float*)d_in[5];
    const float* ln2_g = (const float*)d_in[6];
    const float* ln2_b = (const float*)d_in[7];
    const float* ff_w1 = (const float*)d_in[8];
    const float* ff_b1 = (const float*)d_in[9];
    const float* ff_w2 = (const float*)d_in[10];
    const float* ff_b2 = (const float*)d_in[11];
    float* X = (float*)d_out;

    const int SM_QKV   = 52224;
    const int SM_FUSED = 103424;
    const int SM_ATTN  = (2 * 11664 + 9216) * 4;
    cudaFuncSetAttribute(k_qkv,   cudaFuncAttributeMaxDynamicSharedMemorySize, SM_QKV);
    cudaFuncSetAttribute(k_fused, cudaFuncAttributeMaxDynamicSharedMemorySize, SM_FUSED);
    cudaFuncSetAttribute(k_attn,  cudaFuncAttributeMaxDynamicSharedMemorySize, SM_ATTN);

    cudaMemcpyAsync(X, x_in, (size_t)MTOT * 128 * sizeof(float),
                    cudaMemcpyDeviceToDevice, 0);
    k_prep<<<3072, 256>>>(qkv_w, out_w, ff_w1, ff_w2);

    const int GB = MTOT / 64;    // 2048 CTAs
    dim3 gAttn(8, 8, 8);
    for (int d = 0; d < 4; d++) {
        k_qkv<<<GB, 256, SM_QKV>>>(X, ln1_g + d*128, ln1_b + d*128, d);
        k_attn<<<gAttn, 256, SM_ATTN>>>();
        k_fused<<<GB, 256, SM_FUSED>>>(out_b + d*128, ln2_g + d*128, ln2_b + d*128,
                                       ff_b1 + d*512, ff_b2 + d*128, X, d);
    }
}